// round 5
// baseline (speedup 1.0000x reference)
#include <cuda_runtime.h>

// Slice_windows: (32,1,1024,1024) f32 -> (32,8) f32
//
// R5 design:
//  - Grid 592 = 4 CTAs/SM exactly (no per-SM quantization), 256 thr, 64 regs.
//  - 4096 work items: 128x64 strips (8 strip-rows x 16 strip-cols per image).
//    CTA j owns contiguous items [j*4096/592, (j+1)*4096/592) -> 6-7 items,
//    +1.2% imbalance vs +13.5% in R3/R4. Deterministic static assignment.
//  - Per item: k=2,4 in registers during the gmem pass; k=8 via smem (half
//    the threads); k=16/32/64 by warp 0; strip sum (= half k=128 window) to
//    g_half. Per-item entropy partials (k=2..64) block-reduced, written SoA.
//  - Fused finalize by last-arriving CTA: k<=64 means from SoA partials
//    (contiguous float4 reads), k=128 from half pairs, k=256 from 8 halves.

#define NBATCH   32
#define NCTAS    592            // 4 x 148
#define NTHREADS 256
#define NITEMS   4096           // 32 images x 8 x 16 strips (128 rows x 64 cols)

__device__ float g_item[6 * NITEMS];    // SoA: [level][item], entropy sums k=2..64
__device__ float g_half[NITEMS];        // strip total sum (half of a k=128 window)
__device__ int   g_count = 0;

__device__ __forceinline__ float plogp(float p) {
    // p * log2(p), 0 at p == 0 (matches ref where(p>0,p,1))
    return p * __log2f(fmaxf(p, 1.17549435e-38f));
}
__device__ __forceinline__ float ent(float s, float inv_n) {
    const float p = s * inv_n;
    return plogp(p) + plogp(1.f - p);
}

__global__ void __launch_bounds__(NTHREADS, 4)
slice_windows(const float* __restrict__ x, float* __restrict__ out)
{
    __shared__ float s_k4[512];     // 32x16 k=4 sums
    __shared__ float s_k8[128];     // 16x8
    __shared__ float s_k16[32];     // 8x4
    __shared__ float s_k32[8];      // 4x2
    __shared__ float s_k64[2];      // 2x1
    __shared__ float s_wp[8 * 6];   // per-warp entropy partials
    __shared__ bool  is_last;

    const int tid  = threadIdx.x;
    const int bid  = blockIdx.x;
    const int lane = tid & 31;
    const int warp = tid >> 5;

    const int it0 = (bid * NITEMS) / NCTAS;
    const int it1 = ((bid + 1) * NITEMS) / NCTAS;

    for (int item = it0; item < it1; ++item) {
        const int img = item >> 7;
        const int loc = item & 127;
        const int sr  = loc >> 4;           // strip row 0..7  (128 rows each)
        const int sc  = loc & 15;           // strip col 0..15 (64 cols each)
        const float* __restrict__ base =
            x + (size_t)img * (1024 * 1024) + (size_t)(sr * 128) * 1024 + sc * 64;

        float e0 = 0.f, e1 = 0.f, e2 = 0.f, e3 = 0.f, e4 = 0.f, e5 = 0.f;

        // ---- Gmem pass: 512 4x4 blocks, 2 per thread (rows 4*oy and 4*(oy+16)).
        {
            const int ox = tid & 15;        // col-block 0..15
            const int oy = tid >> 4;        // row-block 0..15
            const float* pA = base + (size_t)(oy * 4) * 1024 + ox * 4;
            const float* pB = pA + (size_t)64 * 1024;
            const float4 a0 = *(const float4*)(pA);
            const float4 a1 = *(const float4*)(pA + 1024);
            const float4 a2 = *(const float4*)(pA + 2048);
            const float4 a3 = *(const float4*)(pA + 3072);
            const float4 b0 = *(const float4*)(pB);
            const float4 b1 = *(const float4*)(pB + 1024);
            const float4 b2 = *(const float4*)(pB + 2048);
            const float4 b3 = *(const float4*)(pB + 3072);
            {
                const float s00 = (a0.x + a0.y) + (a1.x + a1.y);
                const float s01 = (a0.z + a0.w) + (a1.z + a1.w);
                const float s10 = (a2.x + a2.y) + (a3.x + a3.y);
                const float s11 = (a2.z + a2.w) + (a3.z + a3.w);
                e0 -= ent(s00, .25f) + ent(s01, .25f) + ent(s10, .25f) + ent(s11, .25f);
                const float S = (s00 + s01) + (s10 + s11);
                e1 -= ent(S, .0625f);
                s_k4[oy * 16 + ox] = S;
            }
            {
                const float s00 = (b0.x + b0.y) + (b1.x + b1.y);
                const float s01 = (b0.z + b0.w) + (b1.z + b1.w);
                const float s10 = (b2.x + b2.y) + (b3.x + b3.y);
                const float s11 = (b2.z + b2.w) + (b3.z + b3.w);
                e0 -= ent(s00, .25f) + ent(s01, .25f) + ent(s10, .25f) + ent(s11, .25f);
                const float S = (s00 + s01) + (s10 + s11);
                e1 -= ent(S, .0625f);
                s_k4[(oy + 16) * 16 + ox] = S;
            }
        }
        __syncthreads();

        // ---- k=8: 16x8 outputs, threads 0..127
        if (tid < 128) {
            const int oy = tid >> 3, ox = tid & 7;
            const float* r0 = s_k4 + (2 * oy) * 16 + 2 * ox;
            const float s = (r0[0] + r0[1]) + (r0[16] + r0[17]);
            e2 -= ent(s, 1.f / 64.f);
            s_k8[tid] = s;
        }
        __syncthreads();

        // ---- warp 0 tail: k=16, k=32, k=64, strip sum
        if (warp == 0) {
            {
                const int oy = lane >> 2, ox = lane & 3;       // 8x4 = 32
                const float* r0 = s_k8 + (2 * oy) * 8 + 2 * ox;
                const float s = (r0[0] + r0[1]) + (r0[8] + r0[9]);
                e3 -= ent(s, 1.f / 256.f);
                s_k16[lane] = s;
            }
            __syncwarp();
            if (lane < 8) {                                    // 4x2
                const int oy = lane >> 1, ox = lane & 1;
                const float* r0 = s_k16 + (2 * oy) * 4 + 2 * ox;
                const float s = (r0[0] + r0[1]) + (r0[4] + r0[5]);
                e4 -= ent(s, 1.f / 1024.f);
                s_k32[lane] = s;
            }
            __syncwarp();
            if (lane < 2) {                                    // 2x1
                const float* r0 = s_k32 + (2 * lane) * 2;
                const float s = (r0[0] + r0[1]) + (r0[2] + r0[3]);
                e5 -= ent(s, 1.f / 4096.f);
                s_k64[lane] = s;
            }
            __syncwarp();
            if (lane == 0)
                g_half[item] = s_k64[0] + s_k64[1];
        }

        // ---- per-item block reduce of e0..e5
#pragma unroll
        for (int o = 16; o > 0; o >>= 1) {
            e0 += __shfl_down_sync(0xffffffffu, e0, o);
            e1 += __shfl_down_sync(0xffffffffu, e1, o);
            e2 += __shfl_down_sync(0xffffffffu, e2, o);
            e3 += __shfl_down_sync(0xffffffffu, e3, o);
            e4 += __shfl_down_sync(0xffffffffu, e4, o);
            e5 += __shfl_down_sync(0xffffffffu, e5, o);
        }
        if (lane == 0) {
            s_wp[warp * 6 + 0] = e0;  s_wp[warp * 6 + 1] = e1;
            s_wp[warp * 6 + 2] = e2;  s_wp[warp * 6 + 3] = e3;
            s_wp[warp * 6 + 4] = e4;  s_wp[warp * 6 + 5] = e5;
        }
        __syncthreads();
        if (tid < 6) {
            float s = 0.f;
#pragma unroll
            for (int w = 0; w < 8; w++) s += s_wp[w * 6 + tid];
            g_item[tid * NITEMS + item] = s;
        }
        // next item's s_k4 writes are safe: all k4 reads completed before the
        // second __syncthreads above; s_wp reads (tid<6) complete before those
        // threads reach the next item's first __syncthreads.
    }

    // ---- Fused finalize: last-arriving CTA computes the (32,8) output.
    __threadfence();
    if (tid == 0) {
        const int prev = atomicAdd(&g_count, 1);
        is_last = (prev == NCTAS - 1);
    }
    __syncthreads();
    if (is_last) {
        if (tid < 192) {
            // k=2..64 means: (b,l), sum 128 contiguous item partials
            const int b = tid / 6, l = tid - 6 * (tid / 6);
            const float4* gp = (const float4*)(g_item + l * NITEMS + b * 128);
            float4 acc0 = make_float4(0, 0, 0, 0), acc1 = acc0, acc2 = acc0, acc3 = acc0;
#pragma unroll
            for (int i = 0; i < 32; i += 4) {
                const float4 v0 = gp[i], v1 = gp[i + 1], v2 = gp[i + 2], v3 = gp[i + 3];
                acc0.x += v0.x; acc0.y += v0.y; acc0.z += v0.z; acc0.w += v0.w;
                acc1.x += v1.x; acc1.y += v1.y; acc1.z += v1.z; acc1.w += v1.w;
                acc2.x += v2.x; acc2.y += v2.y; acc2.z += v2.z; acc2.w += v2.w;
                acc3.x += v3.x; acc3.y += v3.y; acc3.z += v3.z; acc3.w += v3.w;
            }
            const float s = ((acc0.x + acc0.y) + (acc0.z + acc0.w))
                          + ((acc1.x + acc1.y) + (acc1.z + acc1.w))
                          + ((acc2.x + acc2.y) + (acc2.z + acc2.w))
                          + ((acc3.x + acc3.y) + (acc3.z + acc3.w));
            const int k = 2 << l;             // 2..64
            const int d = 1024 / k;
            out[b * 8 + l] = s / (float)(d * d);
        } else if (tid < 224) {
            // k=128: one thread per image; window = 2 horizontal halves
            const int b = tid - 192;
            const float* h = g_half + b * 128;
            float s = 0.f;
            for (int wr = 0; wr < 8; wr++)
#pragma unroll
                for (int wc = 0; wc < 8; wc++) {
                    const float S = h[wr * 16 + 2 * wc] + h[wr * 16 + 2 * wc + 1];
                    s -= ent(S, 1.f / 16384.f);
                }
            out[b * 8 + 6] = s / 64.f;
        } else {
            // k=256: one thread per image; window = 8 strip sums (2 rows x 4 cols)
            const int b = tid - 224;
            const float* h = g_half + b * 128;
            float s = 0.f;
            for (int wr = 0; wr < 4; wr++)
#pragma unroll
                for (int wc = 0; wc < 4; wc++) {
                    float S = 0.f;
#pragma unroll
                    for (int r = 0; r < 2; r++)
#pragma unroll
                        for (int c = 0; c < 4; c++)
                            S += h[(2 * wr + r) * 16 + 4 * wc + c];
                    s -= ent(S, 1.f / 65536.f);
                }
            out[b * 8 + 7] = s / 16.f;
        }
        if (tid == 0) g_count = 0;            // reset for graph replay
    }
}

extern "C" void kernel_launch(void* const* d_in, const int* in_sizes, int n_in,
                              void* d_out, int out_size)
{
    (void)in_sizes; (void)n_in; (void)out_size;
    const float* x = (const float*)d_in[0];
    float* out = (float*)d_out;
    slice_windows<<<NCTAS, NTHREADS>>>(x, out);
}